// round 13
// baseline (speedup 1.0000x reference)
#include <cuda_runtime.h>
#include <math.h>
#include <stdint.h>

#define BB 64
#define NN 512
#define DD 128
#define MM 128
#define NEG_INF -1e9f

// Scratch (device globals)
__device__ float g_M[DD * DD];         // M[e][d], pre-rounded to tf32
__device__ float g_part[BB * 8 * 128]; // per-(batch,chunk) partial masked sums
__device__ int   g_ccnt[BB * 8];       // per-chunk active counts
__device__ float g_s[BB * NN];         // s_i = a_i^T M a_i (active rows only)
__device__ int   g_arrive[BB];         // per-batch arrival counters (self-resetting)
__device__ int   g_mdone = 0;          // M-producer completion counter
__device__ int   g_done  = 0;          // global block completion counter

__device__ __forceinline__ float warp_sum(float v) {
#pragma unroll
    for (int o = 16; o; o >>= 1) v += __shfl_xor_sync(0xffffffffu, v, o);
    return v;
}
__device__ __forceinline__ float warp_max(float v) {
#pragma unroll
    for (int o = 16; o; o >>= 1) v = fmaxf(v, __shfl_xor_sync(0xffffffffu, v, o));
    return v;
}
__device__ __forceinline__ float dot4(float4 a, float4 b) {
    return a.x * b.x + a.y * b.y + a.z * b.z + a.w * b.w;
}
__device__ __forceinline__ float tf32_rna(float f) {
    uint32_t u;
    asm("cvt.rna.tf32.f32 %0, %1;" : "=r"(u) : "f"(f));
    return __uint_as_float(u);
}
__device__ __forceinline__ void split1(float f, float& hi, float& lo) {
    hi = tf32_rna(f);
    lo = tf32_rna(f - hi);
}
__device__ __forceinline__ void mma_tf32(float* c, const uint32_t* a,
                                         uint32_t b0, uint32_t b1) {
    asm("mma.sync.aligned.m16n8k8.row.col.f32.tf32.tf32.f32 "
        "{%0,%1,%2,%3}, {%4,%5,%6,%7}, {%8,%9}, {%0,%1,%2,%3};"
        : "+f"(c[0]), "+f"(c[1]), "+f"(c[2]), "+f"(c[3])
        : "r"(a[0]), "r"(a[1]), "r"(a[2]), "r"(a[3]), "r"(b0), "r"(b1));
}

// smem byte offsets — every float4-accessed region 16B-aligned
#define OFF_M     0        // 128*34*16 = 69632
#define OFF_A     69632    // 34816
#define OFF_AHI   104448   // 34816
#define OFF_ALO   139264   // 34816
#define OFF_PART  174080   // 4096   (float4 stores)
#define OFF_ASUM  178176   // 512    (scalar)
#define OFF_QS    178688   // 512    (float4 reads)
#define OFF_MASK  179200   // 256    (scalar)
#define OFF_LOC   179456   // 256    (scalar)
#define OFF_SS    179712   // 512    (scalar)
#define OFF_GG    180224   // 512    (float4 reads)   -- 180224 % 16 == 0
#define OFF_WSUM  180736   // 512    (scalar)
#define OFF_SW    181248   // 4096   (float4 stores)  -- 181248 % 16 == 0
#define OFF_SC    185344   // 2048   (scalar)
#define OFF_SRED  187392   // 128    (scalar)
#define OFF_CNT   187520   // 4
#define OFF_LAST  187524   // 4
#define OFF_CV    187528   // 4
#define K_SMEM    187536

#define MST 34   // staged row stride in float4
#define MSTF 136 // staged row stride in floats

__global__ __launch_bounds__(256) void fused_kernel(
    const float* __restrict__ A, const float* __restrict__ mask,
    const float* __restrict__ Wq, const float* __restrict__ Wk,
    const float* __restrict__ bq, const float* __restrict__ bk,
    float* __restrict__ out)
{
    extern __shared__ char smem[];
    float*  sMf   = (float*)(smem + OFF_M);
    float4* sM4   = (float4*)(smem + OFF_M);
    float*  sAf   = (float*)(smem + OFF_A);
    float4* sA4   = (float4*)(smem + OFF_A);
    float*  sAhif = (float*)(smem + OFF_AHI);
    float4* sAhi4 = (float4*)(smem + OFF_AHI);
    float*  sAlof = (float*)(smem + OFF_ALO);
    float4* sAlo4 = (float4*)(smem + OFF_ALO);
    float*  sPart = (float*)(smem + OFF_PART);
    float*  asum  = (float*)(smem + OFF_ASUM);
    float*  qs    = (float*)(smem + OFF_QS);
    float*  sMask = (float*)(smem + OFF_MASK);
    int*    sLoc  = (int*)(smem + OFF_LOC);
    float*  sS    = (float*)(smem + OFF_SS);
    float*  gG    = (float*)(smem + OFF_GG);
    float*  wsum  = (float*)(smem + OFF_WSUM);
    float*  sWf   = (float*)(smem + OFF_SW);
    float*  sc    = (float*)(smem + OFF_SC);
    float*  sRed  = (float*)(smem + OFF_SRED);
    int*    sCnt  = (int*)(smem + OFF_CNT);
    int*    sLast = (int*)(smem + OFF_LAST);
    float*  sCv   = (float*)(smem + OFF_CV);

    const int warp = threadIdx.x >> 5, lane = threadIdx.x & 31, tid = threadIdx.x;
    const int bid = blockIdx.x;
    const int b = bid >> 3;
    const int c = bid & 7;
    const int r0 = c * 64;
    const size_t base = (size_t)b * NN;
    const float4* A4 = (const float4*)A;
    const float4* gM4 = (const float4*)g_M;
    const float4* Wq4 = (const float4*)Wq;
    const float4* Wk4 = (const float4*)Wk;

    // ================= Phase P: M producers (bids 0..15, wave-1 resident) ====
    if (bid < 16) {
        const int d = tid & 127;
        const int e0 = bid * 8 + (tid >> 7) * 4;
        const float4* wq = (const float4*)(Wq + d * MM);
        const float4* wkA = (const float4*)(Wk + (e0 + 0) * MM);
        const float4* wkB = (const float4*)(Wk + (e0 + 1) * MM);
        const float4* wkC = (const float4*)(Wk + (e0 + 2) * MM);
        const float4* wkD = (const float4*)(Wk + (e0 + 3) * MM);
        float a0 = 0.f, a1 = 0.f, a2 = 0.f, a3 = 0.f;
#pragma unroll 8
        for (int m = 0; m < 32; m++) {
            float4 q = wq[m];
            a0 += dot4(q, wkA[m]);
            a1 += dot4(q, wkB[m]);
            a2 += dot4(q, wkC[m]);
            a3 += dot4(q, wkD[m]);
        }
        g_M[(e0 + 0) * DD + d] = tf32_rna(a0);
        g_M[(e0 + 1) * DD + d] = tf32_rna(a1);
        g_M[(e0 + 2) * DD + d] = tf32_rna(a2);
        g_M[(e0 + 3) * DD + d] = tf32_rna(a3);
        __syncthreads();
        if (tid == 0) { __threadfence(); atomicAdd(&g_mdone, 1); }
    }

    // ============ stage A rows (+ hi/lo split), mask (M-independent) =========
#pragma unroll 2
    for (int idx = tid; idx < 2048; idx += 256) {
        int r = idx >> 5, col = idx & 31;
        float4 a = A4[(base + r0 + r) * 32 + col];
        sA4[r * MST + col] = a;
        float4 hi, lo;
        split1(a.x, hi.x, lo.x);
        split1(a.y, hi.y, lo.y);
        split1(a.z, hi.z, lo.z);
        split1(a.w, hi.w, lo.w);
        sAhi4[r * MST + col] = hi;
        sAlo4[r * MST + col] = lo;
    }
    if (tid < 64) { sMask[tid] = mask[base + r0 + tid]; sLoc[tid] = -1; }
    __syncthreads();

    // ---- masked partial sums (warp w -> rows w*8..w*8+7) ----
    {
        float4 acc = make_float4(0.f, 0.f, 0.f, 0.f);
#pragma unroll
        for (int j = 0; j < 8; j++) {
            int r = warp * 8 + j;
            float m = sMask[r];
            float4 a = sA4[r * MST + lane];
            acc.x = fmaf(m, a.x, acc.x);
            acc.y = fmaf(m, a.y, acc.y);
            acc.z = fmaf(m, a.z, acc.z);
            acc.w = fmaf(m, a.w, acc.w);
        }
        ((float4*)(sPart + warp * 128))[lane] = acc;
    }

    // ---- chunk compaction (warp 0) ----
    if (warp == 0) {
        float m0 = sMask[lane];
        float m1 = sMask[32 + lane];
        unsigned b0 = __ballot_sync(0xffffffffu, m0 > 0.f);
        unsigned b1 = __ballot_sync(0xffffffffu, m1 > 0.f);
        int c0 = __popc(b0);
        int pre0 = __popc(b0 & ((1u << lane) - 1u));
        int pre1 = __popc(b1 & ((1u << lane) - 1u));
        if (m0 > 0.f) sLoc[pre0] = lane;
        if (m1 > 0.f) sLoc[c0 + pre1] = 32 + lane;
        if (lane == 0) {
            int tot = c0 + __popc(b1);
            g_ccnt[b * 8 + c] = tot;
            *sCnt = tot;
        }
    }
    __syncthreads();

    // ---- reduce partials to global ----
    if (tid < 128) {
        float s = 0.f;
#pragma unroll
        for (int w = 0; w < 8; w++) s += sPart[w * 128 + tid];
        g_part[((size_t)b * 8 + c) * 128 + tid] = s;
    }

    // ================= wait for M, stage it ==================================
    if (tid == 0) {
        while (atomicAdd(&g_mdone, 0) < 16) __nanosleep(64);
    }
    __syncthreads();
    __threadfence();
#pragma unroll 4
    for (int idx = tid; idx < 4096; idx += 256)
        sM4[(idx >> 5) * MST + (idx & 31)] = gM4[idx];
    __syncthreads();

    // ---- conversion-free split-tf32 tensor-core quadratic form ----
    {
        const int cnt = *sCnt;
        const int rg = warp & 3;    // 16-slot compacted row group
        const int dh = warp >> 2;   // d half (64 cols)
        const int g  = lane >> 2;   // mma group id
        const int tg = lane & 3;    // mma thread-in-group

        if (rg * 16 < cnt) {
            const int slot0 = rg * 16 + g;
            const int slot1 = slot0 + 8;
            const int loc0 = sLoc[slot0];
            const int loc1 = sLoc[slot1];
            const int l0 = (loc0 >= 0) ? loc0 : 0;
            const int l1 = (loc1 >= 0) ? loc1 : 0;

            float acc[8][4];
#pragma unroll
            for (int t = 0; t < 8; t++)
#pragma unroll
                for (int j = 0; j < 4; j++) acc[t][j] = 0.f;

#pragma unroll
            for (int k = 0; k < 16; k++) {
                const int e0 = k * 8;
                uint32_t ah[4], al[4];
                ah[0] = __float_as_uint(sAhif[l0 * MSTF + e0 + tg]);
                ah[1] = __float_as_uint(sAhif[l1 * MSTF + e0 + tg]);
                ah[2] = __float_as_uint(sAhif[l0 * MSTF + e0 + tg + 4]);
                ah[3] = __float_as_uint(sAhif[l1 * MSTF + e0 + tg + 4]);
                al[0] = __float_as_uint(sAlof[l0 * MSTF + e0 + tg]);
                al[1] = __float_as_uint(sAlof[l1 * MSTF + e0 + tg]);
                al[2] = __float_as_uint(sAlof[l0 * MSTF + e0 + tg + 4]);
                al[3] = __float_as_uint(sAlof[l1 * MSTF + e0 + tg + 4]);
#pragma unroll
                for (int t = 0; t < 8; t++) {
                    const int n0 = dh * 64 + t * 8;
                    uint32_t b0 = __float_as_uint(sMf[(e0 + tg) * MSTF + n0 + g]);
                    uint32_t b1 = __float_as_uint(sMf[(e0 + tg + 4) * MSTF + n0 + g]);
                    mma_tf32(acc[t], ah, b0, b1);
                    mma_tf32(acc[t], al, b0, b1);
                }
            }

            float p0 = 0.f, p1 = 0.f;
#pragma unroll
            for (int t = 0; t < 8; t++) {
                const int col = dh * 64 + t * 8 + tg * 2;
                float2 x0 = *(const float2*)&sAf[l0 * MSTF + col];
                float2 x1 = *(const float2*)&sAf[l1 * MSTF + col];
                p0 += acc[t][0] * x0.x + acc[t][1] * x0.y;
                p1 += acc[t][2] * x1.x + acc[t][3] * x1.y;
            }
            p0 += __shfl_xor_sync(0xffffffffu, p0, 1);
            p0 += __shfl_xor_sync(0xffffffffu, p0, 2);
            p1 += __shfl_xor_sync(0xffffffffu, p1, 1);
            p1 += __shfl_xor_sync(0xffffffffu, p1, 2);
            if (tg == 0) {
                sS[dh * 64 + slot0] = p0;
                sS[dh * 64 + slot1] = p1;
            }
        }
    }
    __syncthreads();

    if (tid < 64) {
        int loc = sLoc[tid];
        if (loc >= 0) g_s[base + r0 + loc] = sS[tid] + sS[64 + tid];
    }

    // ================= last-block-of-batch: stats + softmax + context ========
    __threadfence();
    __syncthreads();
    if (tid == 0) {
        int old = atomicAdd(&g_arrive[b], 1);
        *sLast = (old == 7) ? 1 : 0;
    }
    __syncthreads();
    if (*sLast) {
        // ---- stats: asum, qs, C, G ----
        int cnt = 0;
#pragma unroll
        for (int cc = 0; cc < 8; cc++) cnt += g_ccnt[b * 8 + cc];

        if (tid < 128) {
            float s = 0.f;
#pragma unroll
            for (int cc = 0; cc < 8; cc++) s += g_part[((size_t)b * 8 + cc) * 128 + tid];
            asum[tid] = s;
        }
        __syncthreads();

        if (tid < 128) {
            float q = (float)cnt * bq[tid];
#pragma unroll 8
            for (int d = 0; d < DD; d++) q = fmaf(asum[d], Wq[d * MM + tid], q);
            qs[tid] = q;
        }
        __syncthreads();

        if (warp == 0) {
            float cv = 0.f;
            for (int m = lane; m < MM; m += 32) cv = fmaf(bk[m], qs[m] - bq[m], cv);
            cv = warp_sum(cv);
            if (lane == 0) *sCv = cv;
        }

        {
            float4 qs4 = ((const float4*)qs)[lane];
            float4 bk4 = ((const float4*)bk)[lane];
#pragma unroll
            for (int d = warp; d < DD; d += 8) {
                float p = dot4(Wk4[d * 32 + lane], qs4) - dot4(Wq4[d * 32 + lane], bk4);
                p = warp_sum(p);
                if (lane == 0) gG[d] = p;
            }
        }
        if (tid == 0) atomicExch(&g_arrive[b], 0);   // reset for next replay
        __syncthreads();

        // ---- agg: lin - s + C (masked) ----
        {
            float4 G4 = ((const float4*)gG)[lane];
            const float C = *sCv;
#pragma unroll
            for (int i = warp; i < NN; i += 8) {
                float m = mask[base + i];
                float4 a = A4[(base + i) * 32 + lane];
                float lin = dot4(a, G4);
                lin = warp_sum(lin);
                if (lane == 0) sc[i] = (m > 0.f) ? (lin - g_s[base + i] + C) : 0.f;
            }
        }
        __syncthreads();

        // ---- sum of squares -> norm ----
        float ss = 0.f;
        for (int i = tid; i < NN; i += 256) { float v = sc[i]; ss = fmaf(v, v, ss); }
        ss = warp_sum(ss);
        if (lane == 0) sRed[warp] = ss;
        __syncthreads();
        float tot = 0.f;
#pragma unroll
        for (int w = 0; w < 8; w++) tot += sRed[w];
        float inv = rsqrtf(tot);

        // ---- scores + max ----
        float mx = -INFINITY;
        for (int i = tid; i < NN; i += 256) {
            float m = mask[base + i];
            float s = (m > 0.f) ? sc[i] * inv : NEG_INF;
            sc[i] = s;
            mx = fmaxf(mx, s);
        }
        mx = warp_max(mx);
        __syncthreads();
        if (lane == 0) sRed[warp] = mx;
        __syncthreads();
        float Mx = -INFINITY;
#pragma unroll
        for (int w = 0; w < 8; w++) Mx = fmaxf(Mx, sRed[w]);

        // ---- exp & sum ----
        float es = 0.f;
        for (int i = tid; i < NN; i += 256) {
            float e = __expf(sc[i] - Mx);
            sc[i] = e;
            es += e;
        }
        es = warp_sum(es);
        __syncthreads();
        if (lane == 0) sRed[warp] = es;
        __syncthreads();
        float S = 0.f;
#pragma unroll
        for (int w = 0; w < 8; w++) S += sRed[w];
        float invS = 1.0f / S;

        // ---- attn out ----
        for (int i = tid; i < NN; i += 256) {
            float at = sc[i] * invS;
            sc[i] = at;
            out[base + i] = at;
        }
        __syncthreads();

        // ---- wsum[d] = sum_i attn_i * A_i[d] ----
        float4 wacc = make_float4(0.f, 0.f, 0.f, 0.f);
#pragma unroll
        for (int i = warp; i < NN; i += 8) {
            float at = sc[i];
            float4 a = A4[(base + i) * 32 + lane];
            wacc.x = fmaf(at, a.x, wacc.x);
            wacc.y = fmaf(at, a.y, wacc.y);
            wacc.z = fmaf(at, a.z, wacc.z);
            wacc.w = fmaf(at, a.w, wacc.w);
        }
        ((float4*)(sWf + warp * 128))[lane] = wacc;
        __syncthreads();
        if (tid < 128) {
            float s = 0.f;
#pragma unroll
            for (int w = 0; w < 8; w++) s += sWf[w * 128 + tid];
            wsum[tid] = s;
        }
        __syncthreads();

        // ---- context[m] = sum_d wsum[d]*Wk[d,m] + bk[m] ----
        if (tid < 128) {
            float cv = bk[tid];
#pragma unroll 8
            for (int d = 0; d < DD; d++) cv = fmaf(wsum[d], Wk[d * MM + tid], cv);
            out[(size_t)BB * NN + (size_t)b * MM + tid] = cv;
        }
    }

    // ================= global completion: reset producer flag ================
    __syncthreads();
    if (tid == 0) {
        int od = atomicAdd(&g_done, 1);
        if (od == BB * 8 - 1) {
            atomicExch(&g_mdone, 0);
            atomicExch(&g_done, 0);
        }
    }
}

extern "C" void kernel_launch(void* const* d_in, const int* in_sizes, int n_in,
                              void* d_out, int out_size)
{
    const float* A    = (const float*)d_in[0];
    const float* mask = (const float*)d_in[1];
    const float* Wq   = (const float*)d_in[2];
    const float* bq   = (const float*)d_in[3];
    const float* Wk   = (const float*)d_in[4];
    const float* bk   = (const float*)d_in[5];
    float* out = (float*)d_out;

    cudaFuncSetAttribute(fused_kernel,
                         cudaFuncAttributeMaxDynamicSharedMemorySize, K_SMEM);

    fused_kernel<<<BB * 8, 256, K_SMEM>>>(A, mask, Wq, Wk, bq, bk, out);
}

// round 14
// speedup vs baseline: 2.0170x; 2.0170x over previous
#include <cuda_runtime.h>
#include <math.h>
#include <stdint.h>

#define BB 64
#define NN 512
#define DD 128
#define MM 128
#define NEG_INF -1e9f

// Scratch (device globals)
__device__ float g_M[DD * DD];         // M[e][d], pre-rounded to tf32
__device__ float g_part[BB * 8 * 128]; // per-(batch,chunk) partial masked sums
__device__ int   g_ccnt[BB * 8];       // per-chunk active counts
__device__ float g_s[BB * NN];         // s_i = a_i^T M a_i (active rows only)
__device__ float g_G[BB * DD];         // per-batch G vector
__device__ float g_C[BB];              // per-batch scalar
__device__ int   g_arrive[BB];         // per-batch arrival counters (self-resetting)

__device__ __forceinline__ float warp_sum(float v) {
#pragma unroll
    for (int o = 16; o; o >>= 1) v += __shfl_xor_sync(0xffffffffu, v, o);
    return v;
}
__device__ __forceinline__ float warp_max(float v) {
#pragma unroll
    for (int o = 16; o; o >>= 1) v = fmaxf(v, __shfl_xor_sync(0xffffffffu, v, o));
    return v;
}
__device__ __forceinline__ float dot4(float4 a, float4 b) {
    return a.x * b.x + a.y * b.y + a.z * b.z + a.w * b.w;
}
__device__ __forceinline__ float tf32_rna(float f) {
    uint32_t u;
    asm("cvt.rna.tf32.f32 %0, %1;" : "=r"(u) : "f"(f));
    return __uint_as_float(u);
}
__device__ __forceinline__ uint32_t tf32_bits(float f) {
    uint32_t u;
    asm("cvt.rna.tf32.f32 %0, %1;" : "=r"(u) : "f"(f));
    return u;
}
__device__ __forceinline__ void mma_tf32(float* c, const uint32_t* a,
                                         uint32_t b0, uint32_t b1) {
    asm("mma.sync.aligned.m16n8k8.row.col.f32.tf32.tf32.f32 "
        "{%0,%1,%2,%3}, {%4,%5,%6,%7}, {%8,%9}, {%0,%1,%2,%3};"
        : "+f"(c[0]), "+f"(c[1]), "+f"(c[2]), "+f"(c[3])
        : "r"(a[0]), "r"(a[1]), "r"(a[2]), "r"(a[3]), "r"(b0), "r"(b1));
}

// ---------------------------------------------------------------------------
// K0: M[e][d] = Wk row e . Wq row d, stored tf32-rounded.
// ---------------------------------------------------------------------------
__global__ __launch_bounds__(128) void mcol_kernel(
    const float* __restrict__ Wq, const float* __restrict__ Wk)
{
    __shared__ float4 wk[32];
    const int e = blockIdx.x;
    const int d = threadIdx.x;
    if (d < 32) wk[d] = ((const float4*)Wk)[e * 32 + d];
    __syncthreads();

    const float4* wq = (const float4*)(Wq + d * MM);
    float acc = 0.f;
#pragma unroll
    for (int m = 0; m < 32; m++) {
        float4 q = wq[m];
        float4 k = wk[m];
        acc = fmaf(q.x, k.x, acc);
        acc = fmaf(q.y, k.y, acc);
        acc = fmaf(q.z, k.z, acc);
        acc = fmaf(q.w, k.w, acc);
    }
    g_M[e * DD + d] = tf32_rna(acc);
}

// ---------------------------------------------------------------------------
// K1: grid 512 (8 chunks per batch), 256 threads, 110.6KB smem -> 2 blocks/SM.
// Stages M (tf32-in-fp32) and A (fp32). MMA A-operand converted in-loop
// (4 CVT per k-iter). Single MMA per tile (no lo-term).
// Last block per batch computes stats (qs, C, G) inline.
// smem byte offsets (all float4 regions 16B-aligned):
//   M     @0       69632
//   A     @69632   34816
//   part  @104448   4096
//   asum  @108544    512
//   qs    @109056    512
//   mask  @109568    256
//   loc   @109824    256
//   sS    @110080    512
//   cnt   @110592      4
//   last  @110596      4
// ---------------------------------------------------------------------------
#define K1_SMEM 110600
#define MST 34   // staged row stride in float4
#define MSTF 136 // staged row stride in floats

__global__ __launch_bounds__(256, 2) void quad_kernel(
    const float* __restrict__ A, const float* __restrict__ mask,
    const float* __restrict__ Wq, const float* __restrict__ Wk,
    const float* __restrict__ bq, const float* __restrict__ bk)
{
    extern __shared__ char smem[];
    float*  sMf   = (float*)smem;
    float4* sM4   = (float4*)smem;
    float*  sAf   = (float*)(smem + 69632);
    float4* sA4   = (float4*)(smem + 69632);
    float*  sPart = (float*)(smem + 104448);
    float*  asum  = (float*)(smem + 108544);
    float*  qs    = (float*)(smem + 109056);
    float*  sMask = (float*)(smem + 109568);
    int*    sLoc  = (int*)(smem + 109824);
    float*  sS    = (float*)(smem + 110080);
    int*    sCnt  = (int*)(smem + 110592);
    int*    sLast = (int*)(smem + 110596);

    const int warp = threadIdx.x >> 5, lane = threadIdx.x & 31, tid = threadIdx.x;
    const int b = blockIdx.x >> 3;
    const int c = blockIdx.x & 7;
    const int r0 = c * 64;
    const size_t base = (size_t)b * NN;
    const float4* A4 = (const float4*)A;
    const float4* gM4 = (const float4*)g_M;
    const float4* Wq4 = (const float4*)Wq;
    const float4* Wk4 = (const float4*)Wk;

    // ---- stage M, A rows, mask; init sLoc ----
#pragma unroll 4
    for (int idx = tid; idx < 4096; idx += 256)
        sM4[(idx >> 5) * MST + (idx & 31)] = gM4[idx];
#pragma unroll 2
    for (int idx = tid; idx < 2048; idx += 256) {
        int r = idx >> 5, col = idx & 31;
        sA4[r * MST + col] = A4[(base + r0 + r) * 32 + col];
    }
    if (tid < 64) { sMask[tid] = mask[base + r0 + tid]; sLoc[tid] = -1; }
    __syncthreads();

    // ---- masked partial sums (warp w -> rows w*8..w*8+7) ----
    {
        float4 acc = make_float4(0.f, 0.f, 0.f, 0.f);
#pragma unroll
        for (int j = 0; j < 8; j++) {
            int r = warp * 8 + j;
            float m = sMask[r];
            float4 a = sA4[r * MST + lane];
            acc.x = fmaf(m, a.x, acc.x);
            acc.y = fmaf(m, a.y, acc.y);
            acc.z = fmaf(m, a.z, acc.z);
            acc.w = fmaf(m, a.w, acc.w);
        }
        ((float4*)(sPart + warp * 128))[lane] = acc;
    }

    // ---- chunk compaction (warp 0) ----
    if (warp == 0) {
        float m0 = sMask[lane];
        float m1 = sMask[32 + lane];
        unsigned b0 = __ballot_sync(0xffffffffu, m0 > 0.f);
        unsigned b1 = __ballot_sync(0xffffffffu, m1 > 0.f);
        int c0 = __popc(b0);
        int pre0 = __popc(b0 & ((1u << lane) - 1u));
        int pre1 = __popc(b1 & ((1u << lane) - 1u));
        if (m0 > 0.f) sLoc[pre0] = lane;
        if (m1 > 0.f) sLoc[c0 + pre1] = 32 + lane;
        if (lane == 0) {
            int tot = c0 + __popc(b1);
            g_ccnt[b * 8 + c] = tot;
            *sCnt = tot;
        }
    }
    __syncthreads();

    // ---- reduce partials to global ----
    if (tid < 128) {
        float s = 0.f;
#pragma unroll
        for (int w = 0; w < 8; w++) s += sPart[w * 128 + tid];
        g_part[((size_t)b * 8 + c) * 128 + tid] = s;
    }

    // ---- tf32 tensor-core quadratic form (single MMA per tile) ----
    {
        const int cnt = *sCnt;
        const int rg = warp & 3;    // 16-slot compacted row group
        const int dh = warp >> 2;   // d half (64 cols)
        const int g  = lane >> 2;   // mma group id
        const int tg = lane & 3;    // mma thread-in-group

        if (rg * 16 < cnt) {
            const int slot0 = rg * 16 + g;
            const int slot1 = slot0 + 8;
            const int loc0 = sLoc[slot0];
            const int loc1 = sLoc[slot1];
            const int l0 = (loc0 >= 0) ? loc0 : 0;
            const int l1 = (loc1 >= 0) ? loc1 : 0;

            float acc[8][4];
#pragma unroll
            for (int t = 0; t < 8; t++)
#pragma unroll
                for (int j = 0; j < 4; j++) acc[t][j] = 0.f;

#pragma unroll
            for (int k = 0; k < 16; k++) {
                const int e0 = k * 8;
                uint32_t ah[4];
                ah[0] = tf32_bits(sAf[l0 * MSTF + e0 + tg]);
                ah[1] = tf32_bits(sAf[l1 * MSTF + e0 + tg]);
                ah[2] = tf32_bits(sAf[l0 * MSTF + e0 + tg + 4]);
                ah[3] = tf32_bits(sAf[l1 * MSTF + e0 + tg + 4]);
#pragma unroll
                for (int t = 0; t < 8; t++) {
                    const int n0 = dh * 64 + t * 8;
                    uint32_t b0 = __float_as_uint(sMf[(e0 + tg) * MSTF + n0 + g]);
                    uint32_t b1 = __float_as_uint(sMf[(e0 + tg + 4) * MSTF + n0 + g]);
                    mma_tf32(acc[t], ah, b0, b1);
                }
            }

            // s partials: dot Y rows with fp32 A rows
            float p0 = 0.f, p1 = 0.f;
#pragma unroll
            for (int t = 0; t < 8; t++) {
                const int col = dh * 64 + t * 8 + tg * 2;
                float2 x0 = *(const float2*)&sAf[l0 * MSTF + col];
                float2 x1 = *(const float2*)&sAf[l1 * MSTF + col];
                p0 += acc[t][0] * x0.x + acc[t][1] * x0.y;
                p1 += acc[t][2] * x1.x + acc[t][3] * x1.y;
            }
            p0 += __shfl_xor_sync(0xffffffffu, p0, 1);
            p0 += __shfl_xor_sync(0xffffffffu, p0, 2);
            p1 += __shfl_xor_sync(0xffffffffu, p1, 1);
            p1 += __shfl_xor_sync(0xffffffffu, p1, 2);
            if (tg == 0) {
                sS[dh * 64 + slot0] = p0;
                sS[dh * 64 + slot1] = p1;
            }
        }
    }
    __syncthreads();

    if (tid < 64) {
        int loc = sLoc[tid];
        if (loc >= 0) g_s[base + r0 + loc] = sS[tid] + sS[64 + tid];
    }

    // ---- last-block-done: per-batch stats ----
    __threadfence();
    __syncthreads();
    if (tid == 0) {
        int old = atomicAdd(&g_arrive[b], 1);
        *sLast = (old == 7) ? 1 : 0;
    }
    __syncthreads();
    if (*sLast) {
        int cnt = 0;
#pragma unroll
        for (int cc = 0; cc < 8; cc++) cnt += g_ccnt[b * 8 + cc];

        if (tid < 128) {
            float s = 0.f;
#pragma unroll
            for (int cc = 0; cc < 8; cc++) s += g_part[((size_t)b * 8 + cc) * 128 + tid];
            asum[tid] = s;
        }
        __syncthreads();

        if (tid < 128) {
            float q = (float)cnt * bq[tid];
#pragma unroll 8
            for (int d = 0; d < DD; d++) q = fmaf(asum[d], Wq[d * MM + tid], q);
            qs[tid] = q;
        }
        __syncthreads();

        if (warp == 0) {
            float cv = 0.f;
            for (int m = lane; m < MM; m += 32) cv = fmaf(bk[m], qs[m] - bq[m], cv);
            cv = warp_sum(cv);
            if (lane == 0) g_C[b] = cv;
        }

        {
            float4 qs4 = ((const float4*)qs)[lane];
            float4 bk4 = ((const float4*)bk)[lane];
#pragma unroll
            for (int d = warp; d < DD; d += 8) {
                float p = dot4(Wk4[d * 32 + lane], qs4) - dot4(Wq4[d * 32 + lane], bk4);
                p = warp_sum(p);
                if (lane == 0) g_G[b * DD + d] = p;
            }
        }
        if (tid == 0) atomicExch(&g_arrive[b], 0);   // reset for next replay
    }
}

// ---------------------------------------------------------------------------
// K2: per batch (1024 threads): agg = a.G - s + C (masked) -> normalize ->
//     softmax -> attn out; context = wsum@Wk + bk.
// ---------------------------------------------------------------------------
__global__ __launch_bounds__(1024) void softmax_ctx_kernel(
    const float* __restrict__ A, const float* __restrict__ mask,
    const float* __restrict__ Wk, const float* __restrict__ bk,
    float* __restrict__ out)
{
    const int b = blockIdx.x;
    const int warp = threadIdx.x >> 5, lane = threadIdx.x & 31, tid = threadIdx.x;
    const size_t base = (size_t)b * NN;
    const float4* A4 = (const float4*)A;

    __shared__ float sc[NN];
    __shared__ float sRed[32];
    __shared__ float sW[32][128];
    __shared__ float wsum[128];

    // pass 1: agg from linear term + precomputed quadratic term
    {
        float4 G4 = ((const float4*)(g_G + b * DD))[lane];
        const float C = g_C[b];
#pragma unroll
        for (int i = warp; i < NN; i += 32) {
            float m = mask[base + i];
            float4 a = A4[(base + i) * 32 + lane];
            float lin = dot4(a, G4);
            lin = warp_sum(lin);
            float s = g_s[base + i];
            if (lane == 0) sc[i] = (m > 0.f) ? (lin - s + C) : 0.f;
        }
    }
    __syncthreads();

    // sum of squares
    float ss = 0.f;
    for (int i = tid; i < NN; i += 1024) { float v = sc[i]; ss = fmaf(v, v, ss); }
    ss = warp_sum(ss);
    if (lane == 0) sRed[warp] = ss;
    __syncthreads();
    float tot = 0.f;
#pragma unroll
    for (int w = 0; w < 32; w++) tot += sRed[w];
    float inv = rsqrtf(tot);

    // scores + max
    float mx = -INFINITY;
    for (int i = tid; i < NN; i += 1024) {
        float m = mask[base + i];
        float s = (m > 0.f) ? sc[i] * inv : NEG_INF;
        sc[i] = s;
        mx = fmaxf(mx, s);
    }
    mx = warp_max(mx);
    __syncthreads();
    if (lane == 0) sRed[warp] = mx;
    __syncthreads();
    float M = -INFINITY;
#pragma unroll
    for (int w = 0; w < 32; w++) M = fmaxf(M, sRed[w]);

    // exp & sum
    float es = 0.f;
    for (int i = tid; i < NN; i += 1024) {
        float e = __expf(sc[i] - M);
        sc[i] = e;
        es += e;
    }
    es = warp_sum(es);
    __syncthreads();
    if (lane == 0) sRed[warp] = es;
    __syncthreads();
    float S = 0.f;
#pragma unroll
    for (int w = 0; w < 32; w++) S += sRed[w];
    float invS = 1.0f / S;

    // attn out
    for (int i = tid; i < NN; i += 1024) {
        float at = sc[i] * invS;
        sc[i] = at;
        out[base + i] = at;
    }
    __syncthreads();

    // wsum[d] = sum_i attn_i * A_i[d]
    float4 wacc = make_float4(0.f, 0.f, 0.f, 0.f);
#pragma unroll
    for (int i = warp; i < NN; i += 32) {
        float at = sc[i];
        float4 a = A4[(base + i) * 32 + lane];
        wacc.x = fmaf(at, a.x, wacc.x);
        wacc.y = fmaf(at, a.y, wacc.y);
        wacc.z = fmaf(at, a.z, wacc.z);
        wacc.w = fmaf(at, a.w, wacc.w);
    }
    ((float4*)sW[warp])[lane] = wacc;
    __syncthreads();
    if (tid < 128) {
        float s = 0.f;
#pragma unroll
        for (int w = 0; w < 32; w++) s += sW[w][tid];
        wsum[tid] = s;
    }
    __syncthreads();

    if (tid < 128) {
        float c = bk[tid];
#pragma unroll 8
        for (int d = 0; d < DD; d++) c = fmaf(wsum[d], Wk[d * MM + tid], c);
        out[(size_t)BB * NN + (size_t)b * MM + tid] = c;
    }
}

extern "C" void kernel_launch(void* const* d_in, const int* in_sizes, int n_in,
                              void* d_out, int out_size)
{
    const float* A    = (const float*)d_in[0];
    const float* mask = (const float*)d_in[1];
    const float* Wq   = (const float*)d_in[2];
    const float* bq   = (const float*)d_in[3];
    const float* Wk   = (const float*)d_in[4];
    const float* bk   = (const float*)d_in[5];
    float* out = (float*)d_out;

    cudaFuncSetAttribute(quad_kernel,
                         cudaFuncAttributeMaxDynamicSharedMemorySize, K1_SMEM);

    mcol_kernel<<<128, 128>>>(Wq, Wk);
    quad_kernel<<<BB * 8, 256, K1_SMEM>>>(A, mask, Wq, Wk, bq, bk);
    softmax_ctx_kernel<<<BB, 1024>>>(A, mask, Wk, bk, out);
}